// round 12
// baseline (speedup 1.0000x reference)
#include <cuda_runtime.h>
#include <cuda_bf16.h>
#include <stdint.h>
#include <math.h>

#define D    4096
#define RK   1024
#define NTOT (1u << 24)     // 4^12 probability entries
#define PITB 48             // GEMM smem row pitch bytes (16 bf16 + pad) — conflict-free
#define PLNB (128 * PITB)   // 6144 B per plane
#define STGB (12 * PLNB)    // 73728 B per stage (12 planes)
#define TPIT 132            // epilogue transpose pitch (floats)

// ---------------------------------------------------------------------------
// Scratch (__device__ globals per allocation rules).
// ---------------------------------------------------------------------------
__device__ float gA_re[NTOT];
__device__ float gA_im[NTOT];
__device__ float gB_re[NTOT];
__device__ float gB_im[NTOT];
__device__ __nv_bfloat16 gHr[(size_t)D * RK];   // hi(Ur)
__device__ __nv_bfloat16 gLr[(size_t)D * RK];   // lo(Ur)
__device__ __nv_bfloat16 gHi[(size_t)D * RK];   // hi(Ui)
__device__ __nv_bfloat16 gLi[(size_t)D * RK];   // lo(Ui)
__device__ __nv_bfloat16 gHs[(size_t)D * RK];   // hi(Ur+Ui)
__device__ __nv_bfloat16 gLs[(size_t)D * RK];   // lo(Ur+Ui)
__device__ __nv_bfloat16 gHd[(size_t)D * RK];   // hi(Ur-Ui)
__device__ __nv_bfloat16 gLd[(size_t)D * RK];   // lo(Ur-Ui)
__device__ float g_inv_trace;

// ---------------------------------------------------------------------------
static __device__ __forceinline__ void mma16(float c[4], const uint32_t a[4],
                                             const uint32_t b[2]) {
    asm volatile(
        "mma.sync.aligned.m16n8k16.row.col.f32.bf16.bf16.f32 "
        "{%0,%1,%2,%3}, {%4,%5,%6,%7}, {%8,%9}, {%0,%1,%2,%3};\n"
        : "+f"(c[0]), "+f"(c[1]), "+f"(c[2]), "+f"(c[3])
        : "r"(a[0]), "r"(a[1]), "r"(a[2]), "r"(a[3]), "r"(b[0]), "r"(b[1]));
}
static __device__ __forceinline__ uint32_t lds32(const char* base, int off) {
    return *(const uint32_t*)(base + off);
}
static __device__ __forceinline__ void cpa16(void* dstp, const void* src) {
    uint32_t dst = (uint32_t)__cvta_generic_to_shared(dstp);
    asm volatile("cp.async.cg.shared.global [%0], [%1], 16;"
                 :: "r"(dst), "l"(src));
}

// ---------------------------------------------------------------------------
// Pack: for x in {Ur, Ui, Ur+Ui, Ur-Ui}: hi = bf16(x), lo = bf16(x - hi).
// (R6-verified.)
// ---------------------------------------------------------------------------
__global__ void __launch_bounds__(256) pack_split(const float* __restrict__ Ur,
                                                  const float* __restrict__ Ui)
{
    unsigned e = blockIdx.x * 256u + threadIdx.x;   // 0 .. 4M-1
    float ar = Ur[e], ai = Ui[e];
    float s = ar + ai, d = ar - ai;
    __nv_bfloat16 h;
    h = __float2bfloat16_rn(ar); gHr[e] = h; gLr[e] = __float2bfloat16_rn(ar - __bfloat162float(h));
    h = __float2bfloat16_rn(ai); gHi[e] = h; gLi[e] = __float2bfloat16_rn(ai - __bfloat162float(h));
    h = __float2bfloat16_rn(s);  gHs[e] = h; gLs[e] = __float2bfloat16_rn(s  - __bfloat162float(h));
    h = __float2bfloat16_rn(d);  gHd[e] = h; gLd[e] = __float2bfloat16_rn(d  - __bfloat162float(h));
}

// ---------------------------------------------------------------------------
// rho = U U^H via GAUSS 3-product complex GEMM, bf16x3 split, mma.sync.
//   k1 = (a+b)c^T, k2 = a(c+d)^T, k3 = b(c-d)^T ; re = k1-k3, im = k1-k2.
//   (a,b = Ur,Ui rows; c,d = Ur,Ui cols; identity verified R6 on-HW.)
// Tile 128x128, 256 threads, 8 warps (wm 2 x wn 4), warp tile 64x32 (R8 geom).
// K-chunk 16, double-buffered cp.async, 12 smem planes/stage:
//   A-side 0:sH 1:sL 2:aH 3:aL 4:bH 5:bL ; B-side 6:cH 7:cL 8:sH 9:sL 10:dH 11:dL
// MMA per SMSP per k16 = 288 (was 384) -> 0.75x on the legacy-HMMA issue wall.
// Epilogue: main tile float2; mirror via smem transpose (R11, proven).
// ---------------------------------------------------------------------------
__global__ void __launch_bounds__(256, 1) gemm_mma()
{
    extern __shared__ char sm[];    // 2 stages * STGB

    const int tid  = threadIdx.x;
    const int lane = tid & 31;
    const int wid  = tid >> 5;
    const int gid  = lane >> 2;     // 0..7
    const int tig  = lane & 3;      // 0..3
    const int wm   = wid >> 2;      // 0..1
    const int wn   = wid & 3;       // 0..3

    // triangular tile index
    int l = blockIdx.x;
    int bi = (int)((sqrtf(8.0f * (float)l + 1.0f) - 1.0f) * 0.5f);
    while ((bi + 1) * (bi + 2) / 2 <= l) bi++;
    while (bi * (bi + 1) / 2 > l) bi--;
    int bj = l - bi * (bi + 1) / 2;
    const int row0 = bi * 128, col0 = bj * 128;

    // ---- loader: one K-chunk (16 k = 32B/row). 3072 16B-slots / 256 thr = 12 each.
    // slot i = tid + u*256 -> plane u (compile-time), row tid>>1, half tid&1.
    auto load_chunk = [&](int buf, int k0) {
        char* base = sm + buf * STGB;
        int r = tid >> 1, h = tid & 1;
        size_t arow = (size_t)(row0 + r) * RK + k0 + h * 8;
        size_t brow = (size_t)(col0 + r) * RK + k0 + h * 8;
        char* dst = base + r * PITB + h * 16;
        cpa16(dst,              gHs + arow);   // 0: A sH
        cpa16(dst + 1 * PLNB,   gLs + arow);   // 1: A sL
        cpa16(dst + 2 * PLNB,   gHr + arow);   // 2: A aH
        cpa16(dst + 3 * PLNB,   gLr + arow);   // 3: A aL
        cpa16(dst + 4 * PLNB,   gHi + arow);   // 4: A bH
        cpa16(dst + 5 * PLNB,   gLi + arow);   // 5: A bL
        cpa16(dst + 6 * PLNB,   gHr + brow);   // 6: B cH
        cpa16(dst + 7 * PLNB,   gLr + brow);   // 7: B cL
        cpa16(dst + 8 * PLNB,   gHs + brow);   // 8: B sH
        cpa16(dst + 9 * PLNB,   gLs + brow);   // 9: B sL
        cpa16(dst + 10 * PLNB,  gHd + brow);   // 10: B dH
        cpa16(dst + 11 * PLNB,  gLd + brow);   // 11: B dL
    };

    float acc[3][4][4][4];
#pragma unroll
    for (int p = 0; p < 3; p++)
#pragma unroll
        for (int a = 0; a < 4; a++)
#pragma unroll
            for (int b = 0; b < 4; b++)
#pragma unroll
                for (int q = 0; q < 4; q++) acc[p][a][b][q] = 0.f;

    load_chunk(0, 0);
    asm volatile("cp.async.commit_group;");

#pragma unroll 1
    for (int c = 0; c < 64; c++) {
        if (c + 1 < 64) load_chunk((c + 1) & 1, (c + 1) * 16);
        asm volatile("cp.async.commit_group;");
        asm volatile("cp.async.wait_group 1;");
        __syncthreads();

        const char* bb = sm + (c & 1) * STGB;
        const int kbyte = tig * 4;   // word within 32B row

#pragma unroll
        for (int p = 0; p < 3; p++) {
            const char* Abase = bb + (2 * p) * PLNB;       // planes {0,2,4}
            const char* Bbase = bb + (6 + 2 * p) * PLNB;   // planes {6,8,10}

            // ---- B fragments (hi/lo), 4 nf x 2 regs each ----
            uint32_t BH[4][2], BL[4][2];
#pragma unroll
            for (int nf = 0; nf < 4; nf++) {
                int n = (wn * 32 + nf * 8 + gid) * PITB;
                BH[nf][0] = lds32(Bbase,        n + kbyte);
                BH[nf][1] = lds32(Bbase,        n + kbyte + 16);
                BL[nf][0] = lds32(Bbase + PLNB, n + kbyte);
                BL[nf][1] = lds32(Bbase + PLNB, n + kbyte + 16);
            }

#pragma unroll
            for (int mf = 0; mf < 4; mf++) {
                int r = (wm * 64 + mf * 16 + gid) * PITB;
                uint32_t AH[4], AL[4];
                AH[0] = lds32(Abase,        r + kbyte);
                AH[1] = lds32(Abase,        r + 8 * PITB + kbyte);
                AH[2] = lds32(Abase,        r + kbyte + 16);
                AH[3] = lds32(Abase,        r + 8 * PITB + kbyte + 16);
                AL[0] = lds32(Abase + PLNB, r + kbyte);
                AL[1] = lds32(Abase + PLNB, r + 8 * PITB + kbyte);
                AL[2] = lds32(Abase + PLNB, r + kbyte + 16);
                AL[3] = lds32(Abase + PLNB, r + 8 * PITB + kbyte + 16);
                // hh (4 indep), hl, lh
#pragma unroll
                for (int nf = 0; nf < 4; nf++) mma16(acc[p][mf][nf], AH, BH[nf]);
#pragma unroll
                for (int nf = 0; nf < 4; nf++) mma16(acc[p][mf][nf], AH, BL[nf]);
#pragma unroll
                for (int nf = 0; nf < 4; nf++) mma16(acc[p][mf][nf], AL, BH[nf]);
            }
        }
        __syncthreads();
    }

    // drain cp.async before reusing smem for the transpose
    asm volatile("cp.async.wait_group 0;");
    __syncthreads();

    // ---- epilogue: re = k1 - k3, im = k1 - k2 ----
    float accre[4][4][4], accim[4][4][4];
#pragma unroll
    for (int mf = 0; mf < 4; mf++)
#pragma unroll
        for (int nf = 0; nf < 4; nf++)
#pragma unroll
            for (int q = 0; q < 4; q++) {
                accre[mf][nf][q] = acc[0][mf][nf][q] - acc[2][mf][nf][q];
                accim[mf][nf][q] = acc[0][mf][nf][q] - acc[1][mf][nf][q];
            }

    // ---- main tile writes (row-major, float2 per store) ----
#pragma unroll
    for (int mf = 0; mf < 4; mf++)
#pragma unroll
        for (int nf = 0; nf < 4; nf++) {
            unsigned r  = row0 + wm * 64 + mf * 16 + gid;
            unsigned cc = col0 + wn * 32 + nf * 8 + 2 * tig;
            const float* cr = accre[mf][nf];
            const float* ci = accim[mf][nf];
            *(float2*)&gA_re[(size_t)r * D + cc]       = make_float2(cr[0], cr[1]);
            *(float2*)&gA_re[(size_t)(r + 8) * D + cc] = make_float2(cr[2], cr[3]);
            *(float2*)&gA_im[(size_t)r * D + cc]       = make_float2(ci[0], ci[1]);
            *(float2*)&gA_im[(size_t)(r + 8) * D + cc] = make_float2(ci[2], ci[3]);
        }

    // ---- mirror writes via smem transpose (coalesced 512B rows) ----
    if (bi != bj) {
        float* smf = (float*)sm;    // 128 x TPIT floats = 67584 B (< smem)
#pragma unroll 1
        for (int pl = 0; pl < 2; pl++) {
            float sgn = pl ? -1.f : 1.f;
#pragma unroll
            for (int mf = 0; mf < 4; mf++)
#pragma unroll
                for (int nf = 0; nf < 4; nf++) {
                    int rL  = wm * 64 + mf * 16 + gid;
                    int ccL = wn * 32 + nf * 8 + 2 * tig;
                    const float* v = pl ? accim[mf][nf] : accre[mf][nf];
                    smf[(ccL)     * TPIT + rL]     = sgn * v[0];
                    smf[(ccL + 1) * TPIT + rL]     = sgn * v[1];
                    smf[(ccL)     * TPIT + rL + 8] = sgn * v[2];
                    smf[(ccL + 1) * TPIT + rL + 8] = sgn * v[3];
                }
            __syncthreads();
            float* gout = pl ? gA_im : gA_re;
#pragma unroll
            for (int r8 = 0; r8 < 16; r8++) {
                int mr = wid * 16 + r8;
                float4 v = *(float4*)&smf[mr * TPIT + lane * 4];
                *(float4*)&gout[(size_t)(col0 + mr) * D + row0 + lane * 4] = v;
            }
            __syncthreads();
        }
    }
}

// ---------------------------------------------------------------------------
// trace: sum of re diagonal of rho -> 1/trace
// ---------------------------------------------------------------------------
__global__ void trace_kernel()
{
    __shared__ float red[256];
    float s = 0.f;
    for (int i = threadIdx.x; i < D; i += 256)
        s += gA_re[(size_t)i * D + i];
    red[threadIdx.x] = s;
    __syncthreads();
    for (int w = 128; w; w >>= 1) {
        if (threadIdx.x < w) red[threadIdx.x] += red[threadIdx.x + w];
        __syncthreads();
    }
    if (threadIdx.x == 0) g_inv_trace = 1.0f / red[0];
}

// ---------------------------------------------------------------------------
// Fused 2-qubit partial-trace sweep, factored into two 4-term complex stages.
// dir=0: A->B, dir=1: B->A. wim=0 skips imag store (last sweep).
// ---------------------------------------------------------------------------
__global__ void __launch_bounds__(256) qmt_sweep(int dir,
                                                 const float* __restrict__ Mr,
                                                 const float* __restrict__ Mi,
                                                 int lc, int wim)
{
    const float* __restrict__ in_re = dir ? gB_re : gA_re;
    const float* __restrict__ in_im = dir ? gB_im : gA_im;
    float* __restrict__ o_re = dir ? gA_re : gB_re;
    float* __restrict__ o_im = dir ? gA_im : gB_im;

    __shared__ float sr[16], si[16];   // M[s,i,j] at s*4+i*2+j
    int tid = threadIdx.x;
    if (tid < 16) { sr[tid] = Mr[tid]; si[tid] = Mi[tid]; }
    __syncthreads();

    unsigned gid = blockIdx.x * 256u + (unsigned)tid;   // 0 .. 2^20-1
    unsigned cp = 1u << lc;
    unsigned t = gid & (cp - 1u);
    unsigned a = (gid >> lc) & (cp - 1u);
    unsigned k = gid >> (2 * lc);
    unsigned base_in = k << (2 * lc + 4);

    float xr[16], xi[16];
#pragma unroll
    for (int J = 0; J < 4; J++)
#pragma unroll
        for (int I = 0; I < 4; I++) {
            unsigned off = base_in
                         + ((((unsigned)J << lc) + a) << (lc + 2))
                         + ((unsigned)I << lc) + t;
            xr[J * 4 + I] = in_re[off];
            xi[J * 4 + I] = in_im[off];
        }

    // stage 1: contract (j1,i1): y[s1][(j2,i2)]
    float yr[16], yi[16];
#pragma unroll
    for (int s1 = 0; s1 < 4; s1++)
#pragma unroll
        for (int j2 = 0; j2 < 2; j2++)
#pragma unroll
            for (int i2 = 0; i2 < 2; i2++) {
                float ar = 0.f, ai = 0.f;
#pragma unroll
                for (int j1 = 0; j1 < 2; j1++)
#pragma unroll
                    for (int i1 = 0; i1 < 2; i1++) {
                        float mr = sr[s1 * 4 + i1 * 2 + j1];
                        float mi = si[s1 * 4 + i1 * 2 + j1];
                        float vr = xr[(j1 * 2 + j2) * 4 + i1 * 2 + i2];
                        float vi = xi[(j1 * 2 + j2) * 4 + i1 * 2 + i2];
                        ar = fmaf(mr, vr, ar); ar = fmaf(-mi, vi, ar);
                        ai = fmaf(mr, vi, ai); ai = fmaf(mi, vr, ai);
                    }
                yr[s1 * 4 + j2 * 2 + i2] = ar;
                yi[s1 * 4 + j2 * 2 + i2] = ai;
            }

    // stage 2: contract (j2,i2)
#pragma unroll
    for (int s1 = 0; s1 < 4; s1++)
#pragma unroll
        for (int s2 = 0; s2 < 4; s2++) {
            float aR = 0.f, aI = 0.f;
#pragma unroll
            for (int j2 = 0; j2 < 2; j2++)
#pragma unroll
                for (int i2 = 0; i2 < 2; i2++) {
                    float mr = sr[s2 * 4 + i2 * 2 + j2];
                    float mi = si[s2 * 4 + i2 * 2 + j2];
                    float vr = yr[s1 * 4 + j2 * 2 + i2];
                    float vi = yi[s1 * 4 + j2 * 2 + i2];
                    aR = fmaf(mr, vr, aR); aR = fmaf(-mi, vi, aR);
                    aI = fmaf(mr, vi, aI); aI = fmaf(mi, vr, aI);
                }
            unsigned off = (((k << 4) + (unsigned)(s1 * 4 + s2)) << (2 * lc))
                         + (a << lc) + t;
            o_re[off] = aR;
            if (wim) o_im[off] = aI;
        }
}

// ---------------------------------------------------------------------------
// Gather: out[i] = P_all[idx[i]] / trace (real plane only; int32 indices).
// ---------------------------------------------------------------------------
__global__ void gather_kernel(const int* __restrict__ idx,
                              float* __restrict__ out, int n)
{
    int i = blockIdx.x * 256 + threadIdx.x;
    if (i < n) out[i] = gA_re[(unsigned)idx[i] & (NTOT - 1u)] * g_inv_trace;
}

// ---------------------------------------------------------------------------
extern "C" void kernel_launch(void* const* d_in, const int* in_sizes, int n_in,
                              void* d_out, int out_size)
{
    const float* params = (const float*)d_in[0];      // (2, 4096, 1024)
    const float* Mr = (const float*)d_in[1];          // (4,2,2)
    const float* Mi = (const float*)d_in[2];          // (4,2,2)
    const int* idx = (const int*)d_in[3];             // (1e6,) int32
    float* out = (float*)d_out;

    const float* Ur = params;
    const float* Ui = params + (size_t)D * RK;

    pack_split<<<16384, 256>>>(Ur, Ui);

    const int smem_bytes = 2 * STGB;                  // 147456
    cudaFuncSetAttribute(gemm_mma,
                         cudaFuncAttributeMaxDynamicSharedMemorySize, smem_bytes);
    gemm_mma<<<528, 256, smem_bytes>>>();

    trace_kernel<<<1, 256>>>();

    int dir = 0;
    for (int n = 1; n <= 6; n++) {
        qmt_sweep<<<4096, 256>>>(dir, Mr, Mi, 12 - 2 * n, n < 6 ? 1 : 0);
        dir ^= 1;
    }
    // final result (real plane) in gA_re

    int nq = in_sizes[3];
    gather_kernel<<<(nq + 255) / 256, 256>>>(idx, out, nq);
}